// round 4
// baseline (speedup 1.0000x reference)
#include <cuda_runtime.h>

#define BB 4
#define NN 4096
#define CC 128
#define NROWS (BB*NN)       // 16384
#define NCHUNK 32
#define TOTCHUNK (BB*NCHUNK)
#define XS_STRIDE 132
#define MAXFLAG 2048

// ---- scratch (device globals) ----
__device__ float  g_Q [NROWS*CC];       // projected q (raw fp32, cublas-order bits)
__device__ float  g_K [NROWS*CC];       // projected k (raw fp32)
__device__ float  g_Kh[NROWS*CC];       // k / kn
__device__ float  g_V [NROWS*CC];
__device__ float  g_qnorm[NROWS];
__device__ float  g_knorm[NROWS];
__device__ float  g_Mpart[(size_t)TOTCHUNK*CC*CC];
__device__ double g_spart[TOTCHUNK*CC];
__device__ float  g_M[BB*CC*CC];
__device__ double g_s[BB*CC];
__device__ double g_t[BB*CC];
__device__ double g_beta[BB];
__device__ double g_den[NROWS];         // qn * (den_ref + 1e-8)
__device__ int    g_flagcount;
__device__ int    g_flagrows[MAXFLAG];
__device__ double g_bpart[MAXFLAG*8];

// ============================================================
__global__ void zero_kernel() { if (threadIdx.x == 0) g_flagcount = 0; }

// ============================================================
// Kernel 1: Y = X @ W^T + b (fp32, strict ascending-k single-accumulator
// FMA chain, bias added AFTER — mimics cublas sgemm arithmetic).
// z==0: q (+qn).  z==1: k (+kn, +k̂).  z==2: v.
// ============================================================
__global__ void __launch_bounds__(256, 1) proj_kernel(
    const float* __restrict__ q_in, const float* __restrict__ k_in,
    const float* __restrict__ v_in, const float* __restrict__ W,
    const float* __restrict__ bias)
{
    extern __shared__ float sm[];
    float* Ws = sm;                     // Ws[c][d] = W[d][c]
    float* Xs = sm + 128*XS_STRIDE;

    const int tid = threadIdx.x;
    const int tx  = tid & 15;
    const int ty  = tid >> 4;
    const int z   = blockIdx.y;
    const float* X = (z == 0) ? q_in : (z == 1) ? k_in : v_in;
    const int row0 = blockIdx.x * 128;

    for (int i = tid; i < CC*CC; i += 256) {
        int d = i >> 7, c = i & 127;
        Ws[c*XS_STRIDE + d] = W[i];
    }

    float acc[8][8];
    #pragma unroll
    for (int i = 0; i < 8; i++)
        #pragma unroll
        for (int j = 0; j < 8; j++) acc[i][j] = 0.f;

    for (int c0 = 0; c0 < CC; c0 += 32) {
        __syncthreads();
        for (int t = tid; t < 128*8; t += 256) {
            int r = t >> 3, cg = t & 7;
            float4 v = *(const float4*)(X + (size_t)(row0 + r)*CC + c0 + cg*4);
            Xs[(cg*4+0)*XS_STRIDE + r] = v.x;
            Xs[(cg*4+1)*XS_STRIDE + r] = v.y;
            Xs[(cg*4+2)*XS_STRIDE + r] = v.z;
            Xs[(cg*4+3)*XS_STRIDE + r] = v.w;
        }
        __syncthreads();
        #pragma unroll 4
        for (int kk = 0; kk < 32; kk++) {
            float a[8], bb[8];
            *(float4*)&a[0]  = *(float4*)&Xs[kk*XS_STRIDE + ty*8];
            *(float4*)&a[4]  = *(float4*)&Xs[kk*XS_STRIDE + ty*8 + 4];
            *(float4*)&bb[0] = *(float4*)&Ws[(c0+kk)*XS_STRIDE + tx*8];
            *(float4*)&bb[4] = *(float4*)&Ws[(c0+kk)*XS_STRIDE + tx*8 + 4];
            #pragma unroll
            for (int i = 0; i < 8; i++)
                #pragma unroll
                for (int j = 0; j < 8; j++)
                    acc[i][j] = fmaf(a[i], bb[j], acc[i][j]);
        }
    }

    float bj[8];
    *(float4*)&bj[0] = *(const float4*)&bias[tx*8];
    *(float4*)&bj[4] = *(const float4*)&bias[tx*8 + 4];
    #pragma unroll
    for (int i = 0; i < 8; i++)
        #pragma unroll
        for (int j = 0; j < 8; j++) acc[i][j] += bj[j];

    float nrm[8];
    if (z < 2) {
        #pragma unroll
        for (int i = 0; i < 8; i++) {
            float sq = 0.f;
            #pragma unroll
            for (int j = 0; j < 8; j++) sq = fmaf(acc[i][j], acc[i][j], sq);
            #pragma unroll
            for (int off = 8; off; off >>= 1)
                sq += __shfl_xor_sync(0xffffffffu, sq, off, 16);
            nrm[i] = sqrtf(sq);
            if (tx == 0) {
                if (z == 0) g_qnorm[row0 + ty*8 + i] = nrm[i];
                else        g_knorm[row0 + ty*8 + i] = nrm[i];
            }
        }
    }

    #pragma unroll
    for (int i = 0; i < 8; i++) {
        const size_t off = (size_t)(row0 + ty*8 + i)*CC + tx*8;
        if (z == 0) {
            *(float4*)(g_Q + off)     = *(float4*)&acc[i][0];
            *(float4*)(g_Q + off + 4) = *(float4*)&acc[i][4];
        } else if (z == 2) {
            *(float4*)(g_V + off)     = *(float4*)&acc[i][0];
            *(float4*)(g_V + off + 4) = *(float4*)&acc[i][4];
        } else {
            *(float4*)(g_K + off)     = *(float4*)&acc[i][0];
            *(float4*)(g_K + off + 4) = *(float4*)&acc[i][4];
            const float inv = 1.f / nrm[i];
            float4 o0, o1;
            o0.x = acc[i][0]*inv; o0.y = acc[i][1]*inv;
            o0.z = acc[i][2]*inv; o0.w = acc[i][3]*inv;
            o1.x = acc[i][4]*inv; o1.y = acc[i][5]*inv;
            o1.z = acc[i][6]*inv; o1.w = acc[i][7]*inv;
            *(float4*)(g_Kh + off)     = o0;
            *(float4*)(g_Kh + off + 4) = o1;
        }
    }
}

// ============================================================
// Kernel 2: partial M = K̂^T V ; partial s (fp64).
// ============================================================
__global__ void __launch_bounds__(256) kv_kernel()
{
    extern __shared__ float sm[];
    float* Ks = sm;
    float* Vs = sm + CC*CC;
    const int tid = threadIdx.x;
    const int tx  = tid & 15;
    const int ty  = tid >> 4;
    const int blk = blockIdx.x;
    const size_t base = (size_t)blk * 128 * CC;

    const float4* K4 = (const float4*)(g_Kh + base);
    const float4* V4 = (const float4*)(g_V  + base);
    for (int t = tid; t < 4096; t += 256) {
        ((float4*)Ks)[t] = K4[t];
        ((float4*)Vs)[t] = V4[t];
    }
    __syncthreads();

    float acc[8][8] = {};
    #pragma unroll 4
    for (int n = 0; n < 128; n++) {
        float a[8], bb[8];
        *(float4*)&a[0]  = *(float4*)&Ks[n*CC + ty*8];
        *(float4*)&a[4]  = *(float4*)&Ks[n*CC + ty*8 + 4];
        *(float4*)&bb[0] = *(float4*)&Vs[n*CC + tx*8];
        *(float4*)&bb[4] = *(float4*)&Vs[n*CC + tx*8 + 4];
        #pragma unroll
        for (int i = 0; i < 8; i++)
            #pragma unroll
            for (int j = 0; j < 8; j++)
                acc[i][j] = fmaf(a[i], bb[j], acc[i][j]);
    }

    if (tid < 128) {
        double s = 0.0;
        #pragma unroll 8
        for (int n = 0; n < 128; n++) s += (double)Ks[n*CC + tid];
        g_spart[blk*CC + tid] = s;
    }

    float* Mp = g_Mpart + (size_t)blk*CC*CC;
    #pragma unroll
    for (int i = 0; i < 8; i++) {
        float* mrow = Mp + (size_t)(ty*8 + i)*CC + tx*8;
        *(float4*)mrow       = *(float4*)&acc[i][0];
        *(float4*)(mrow + 4) = *(float4*)&acc[i][4];
    }
}

// ============================================================
__global__ void __launch_bounds__(256) reduce_kernel()
{
    const int idx = blockIdx.x*256 + threadIdx.x;
    const int b = idx >> 14;
    const int e = idx & 16383;
    double a = 0.0;
    #pragma unroll
    for (int p = 0; p < NCHUNK; p++)
        a += (double)g_Mpart[(size_t)((b << 5) + p)*CC*CC + e];
    g_M[idx] = (float)a;

    if (blockIdx.x < 2) {
        const int t2 = blockIdx.x*256 + threadIdx.x;
        const int b2 = t2 >> 7, i2 = t2 & 127;
        double s = 0.0;
        #pragma unroll
        for (int p = 0; p < NCHUNK; p++)
            s += g_spart[((b2 << 5) + p)*CC + i2];
        g_s[t2] = s;
    }
}

// ============================================================
__global__ void __launch_bounds__(128) t_kernel(
    const float* __restrict__ W, const float* __restrict__ bias)
{
    const int b = blockIdx.x;
    const int c = threadIdx.x;
    double t = 0.0;
    for (int d = 0; d < CC; d++)
        t += (double)W[d*CC + c] * g_s[b*CC + d];
    g_t[b*CC + c] = t;
    if (c == 0) {
        double be = 0.0;
        for (int d = 0; d < CC; d++)
            be += (double)bias[d] * g_s[b*CC + d];
        g_beta[b] = be;
    }
}

// ============================================================
// Kernel: exact den (fp64) + flag ill-conditioned rows (|den_ref| < 2).
// ============================================================
__global__ void __launch_bounds__(256) den_kernel(const float* __restrict__ x)
{
    const int w = (blockIdx.x << 3) + (threadIdx.x >> 5);
    const int lane = threadIdx.x & 31;
    const int b = w >> 12;
    const float* xr = x + (size_t)w*CC;
    const double* t = g_t + b*CC;
    double s = 0.0;
    #pragma unroll
    for (int u = 0; u < 4; u++)
        s += (double)xr[lane + u*32] * t[lane + u*32];
    #pragma unroll
    for (int off = 16; off; off >>= 1)
        s += __shfl_xor_sync(0xffffffffu, s, off);
    if (lane == 0) {
        const double qn = (double)g_qnorm[w];
        const double num = s + g_beta[b];          // q . s_vec (exact-ish)
        g_den[w] = num + 1e-8 * qn;                // qn * (den_ref + 1e-8)
        if (fabs(num / qn) < 2.0) {
            int slot = atomicAdd(&g_flagcount, 1);
            if (slot < MAXFLAG) g_flagrows[slot] = w;
        }
    }
}

// ============================================================
// Brute-force reference-replica den for flagged rows.
// score = fp32 ascending-k single-accumulator FMA (cublas order);
// cos = score / (qn*kn + 1e-8f) in fp32; sum in fp64.
// grid = (MAXFLAG, 8 chunks of 512 keys), 256 threads (2 keys each).
// ============================================================
__global__ void __launch_bounds__(256) brute_kernel()
{
    const int slot = blockIdx.x;
    if (slot >= g_flagcount || slot >= MAXFLAG) return;
    const int chunk = blockIdx.y;
    const int w = g_flagrows[slot];
    const int b = w >> 12;
    __shared__ float qs[128];
    __shared__ float qn_s;
    __shared__ double red[256];
    const int tid = threadIdx.x;
    if (tid < 128) qs[tid] = g_Q[(size_t)w*CC + tid];
    if (tid == 0) qn_s = g_qnorm[w];
    __syncthreads();

    double local = 0.0;
    #pragma unroll
    for (int r = 0; r < 2; r++) {
        const int j = chunk*512 + r*256 + tid;
        const float* krow = g_K + ((size_t)b*NN + j)*CC;
        float acc = 0.f;
        #pragma unroll 8
        for (int c = 0; c < 128; c++) acc = fmaf(qs[c], krow[c], acc);
        const float d = qn_s * g_knorm[b*NN + j] + 1e-8f;
        local += (double)(acc / d);
    }
    red[tid] = local;
    __syncthreads();
    for (int off = 128; off; off >>= 1) {
        if (tid < off) red[tid] += red[tid + off];
        __syncthreads();
    }
    if (tid == 0) g_bpart[slot*8 + chunk] = red[0];
}

// ============================================================
__global__ void __launch_bounds__(256) combine_kernel()
{
    const int slot = blockIdx.x*256 + threadIdx.x;
    if (slot >= g_flagcount || slot >= MAXFLAG) return;
    const int w = g_flagrows[slot];
    double s = 0.0;
    #pragma unroll
    for (int c = 0; c < 8; c++) s += g_bpart[slot*8 + c];
    g_den[w] = (double)g_qnorm[w] * (s + 1e-8);
}

// ============================================================
__global__ void __launch_bounds__(256, 2) out_kernel(float* __restrict__ out)
{
    extern __shared__ float sm[];
    float* Ms = sm;
    float* Xs = sm + CC*CC;

    const int tid = threadIdx.x;
    const int tx  = tid & 15;
    const int ty  = tid >> 4;
    const int b   = blockIdx.x >> 5;
    const int row0 = blockIdx.x * 128;

    const float4* M4 = (const float4*)(g_M + (size_t)b*CC*CC);
    for (int t = tid; t < 4096; t += 256) ((float4*)Ms)[t] = M4[t];

    float acc[8][8] = {};

    for (int c0 = 0; c0 < CC; c0 += 32) {
        __syncthreads();
        for (int t = tid; t < 128*8; t += 256) {
            int r = t >> 3, cg = t & 7;
            float4 v = *(const float4*)(g_Q + (size_t)(row0 + r)*CC + c0 + cg*4);
            Xs[(cg*4+0)*XS_STRIDE + r] = v.x;
            Xs[(cg*4+1)*XS_STRIDE + r] = v.y;
            Xs[(cg*4+2)*XS_STRIDE + r] = v.z;
            Xs[(cg*4+3)*XS_STRIDE + r] = v.w;
        }
        __syncthreads();
        #pragma unroll 4
        for (int kk = 0; kk < 32; kk++) {
            float a[8], bb[8];
            *(float4*)&a[0]  = *(float4*)&Xs[kk*XS_STRIDE + ty*8];
            *(float4*)&a[4]  = *(float4*)&Xs[kk*XS_STRIDE + ty*8 + 4];
            *(float4*)&bb[0] = *(float4*)&Ms[(c0+kk)*CC + tx*8];
            *(float4*)&bb[4] = *(float4*)&Ms[(c0+kk)*CC + tx*8 + 4];
            #pragma unroll
            for (int i = 0; i < 8; i++)
                #pragma unroll
                for (int j = 0; j < 8; j++)
                    acc[i][j] = fmaf(a[i], bb[j], acc[i][j]);
        }
    }

    #pragma unroll
    for (int i = 0; i < 8; i++) {
        const double inv = 1.0 / g_den[row0 + ty*8 + i];
        float4 o0, o1;
        o0.x = (float)(acc[i][0]*inv); o0.y = (float)(acc[i][1]*inv);
        o0.z = (float)(acc[i][2]*inv); o0.w = (float)(acc[i][3]*inv);
        o1.x = (float)(acc[i][4]*inv); o1.y = (float)(acc[i][5]*inv);
        o1.z = (float)(acc[i][6]*inv); o1.w = (float)(acc[i][7]*inv);
        float* orow = out + (size_t)(row0 + ty*8 + i)*CC + tx*8;
        *(float4*)orow       = o0;
        *(float4*)(orow + 4) = o1;
    }
}

// ============================================================
extern "C" void kernel_launch(void* const* d_in, const int* in_sizes, int n_in,
                              void* d_out, int out_size)
{
    const float* q    = (const float*)d_in[0];
    const float* k    = (const float*)d_in[1];
    const float* v    = (const float*)d_in[2];
    const float* W    = (const float*)d_in[3];
    const float* bias = (const float*)d_in[4];
    float* out = (float*)d_out;

    const size_t sm1 = (size_t)(128 + 32) * XS_STRIDE * sizeof(float);
    const size_t sm2 = (size_t)2 * CC * CC * sizeof(float);
    const size_t sm3 = (size_t)(CC*CC + 32*XS_STRIDE) * sizeof(float);

    cudaFuncSetAttribute(proj_kernel, cudaFuncAttributeMaxDynamicSharedMemorySize, (int)sm1);
    cudaFuncSetAttribute(kv_kernel,   cudaFuncAttributeMaxDynamicSharedMemorySize, (int)sm2);
    cudaFuncSetAttribute(out_kernel,  cudaFuncAttributeMaxDynamicSharedMemorySize, (int)sm3);

    zero_kernel  <<<1, 32>>>();
    proj_kernel  <<<dim3(NROWS/128, 3), 256, sm1>>>(q, k, v, W, bias);
    kv_kernel    <<<TOTCHUNK, 256, sm2>>>();
    reduce_kernel<<<BB*CC*CC/256, 256>>>();
    t_kernel     <<<BB, 128>>>(W, bias);
    den_kernel   <<<NROWS/8, 256>>>(q);
    brute_kernel <<<dim3(MAXFLAG, 8), 256>>>();
    combine_kernel<<<MAXFLAG/256, 256>>>();
    out_kernel   <<<NROWS/128, 256, sm3>>>(out);
}

// round 5
// speedup vs baseline: 4.1647x; 4.1647x over previous
#include <cuda_runtime.h>

#define BB 4
#define NN 4096
#define CC 128
#define NROWS (BB*NN)       // 16384
#define NCHUNK 32
#define TOTCHUNK (BB*NCHUNK)
#define XS_STRIDE 132
#define BSTRIDE 132         // brute smem stride

// ---- scratch (device globals) ----
__device__ float  g_Q [NROWS*CC];
__device__ float  g_K [NROWS*CC];
__device__ float  g_Kh[NROWS*CC];
__device__ float  g_V [NROWS*CC];
__device__ float  g_qnorm[NROWS];
__device__ float  g_knorm[NROWS];
__device__ float  g_Mpart[(size_t)TOTCHUNK*CC*CC];
__device__ double g_spart[TOTCHUNK*CC];
__device__ float  g_M[BB*CC*CC];
__device__ double g_s[BB*CC];
__device__ double g_t[BB*CC];
__device__ double g_beta[BB];
__device__ double g_den[NROWS];
__device__ int    g_flag[NROWS];
__device__ int    g_bcount[BB];
__device__ int    g_list[BB*256];
__device__ double g_bpart[BB*256*32];

// ============================================================
// Kernel 1: Y = X @ W^T + b (fp32, ascending-k single-accumulator FMA).
// z==0: q (+qn).  z==1: k (+kn, +k̂).  z==2: v.
// ============================================================
__global__ void __launch_bounds__(256, 1) proj_kernel(
    const float* __restrict__ q_in, const float* __restrict__ k_in,
    const float* __restrict__ v_in, const float* __restrict__ W,
    const float* __restrict__ bias)
{
    extern __shared__ float sm[];
    float* Ws = sm;                     // Ws[c][d] = W[d][c]
    float* Xs = sm + 128*XS_STRIDE;

    const int tid = threadIdx.x;
    const int tx  = tid & 15;
    const int ty  = tid >> 4;
    const int z   = blockIdx.y;
    const float* X = (z == 0) ? q_in : (z == 1) ? k_in : v_in;
    const int row0 = blockIdx.x * 128;

    for (int i = tid; i < CC*CC; i += 256) {
        int d = i >> 7, c = i & 127;
        Ws[c*XS_STRIDE + d] = W[i];
    }

    float acc[8][8];
    #pragma unroll
    for (int i = 0; i < 8; i++)
        #pragma unroll
        for (int j = 0; j < 8; j++) acc[i][j] = 0.f;

    for (int c0 = 0; c0 < CC; c0 += 32) {
        __syncthreads();
        for (int t = tid; t < 128*8; t += 256) {
            int r = t >> 3, cg = t & 7;
            float4 v = *(const float4*)(X + (size_t)(row0 + r)*CC + c0 + cg*4);
            Xs[(cg*4+0)*XS_STRIDE + r] = v.x;
            Xs[(cg*4+1)*XS_STRIDE + r] = v.y;
            Xs[(cg*4+2)*XS_STRIDE + r] = v.z;
            Xs[(cg*4+3)*XS_STRIDE + r] = v.w;
        }
        __syncthreads();
        #pragma unroll 4
        for (int kk = 0; kk < 32; kk++) {
            float a[8], bb[8];
            *(float4*)&a[0]  = *(float4*)&Xs[kk*XS_STRIDE + ty*8];
            *(float4*)&a[4]  = *(float4*)&Xs[kk*XS_STRIDE + ty*8 + 4];
            *(float4*)&bb[0] = *(float4*)&Ws[(c0+kk)*XS_STRIDE + tx*8];
            *(float4*)&bb[4] = *(float4*)&Ws[(c0+kk)*XS_STRIDE + tx*8 + 4];
            #pragma unroll
            for (int i = 0; i < 8; i++)
                #pragma unroll
                for (int j = 0; j < 8; j++)
                    acc[i][j] = fmaf(a[i], bb[j], acc[i][j]);
        }
    }

    float bj[8];
    *(float4*)&bj[0] = *(const float4*)&bias[tx*8];
    *(float4*)&bj[4] = *(const float4*)&bias[tx*8 + 4];
    #pragma unroll
    for (int i = 0; i < 8; i++)
        #pragma unroll
        for (int j = 0; j < 8; j++) acc[i][j] += bj[j];

    float nrm[8];
    if (z < 2) {
        #pragma unroll
        for (int i = 0; i < 8; i++) {
            float sq = 0.f;
            #pragma unroll
            for (int j = 0; j < 8; j++) sq = fmaf(acc[i][j], acc[i][j], sq);
            #pragma unroll
            for (int off = 8; off; off >>= 1)
                sq += __shfl_xor_sync(0xffffffffu, sq, off, 16);
            nrm[i] = sqrtf(sq);
            if (tx == 0) {
                if (z == 0) g_qnorm[row0 + ty*8 + i] = nrm[i];
                else        g_knorm[row0 + ty*8 + i] = nrm[i];
            }
        }
    }

    #pragma unroll
    for (int i = 0; i < 8; i++) {
        const size_t off = (size_t)(row0 + ty*8 + i)*CC + tx*8;
        if (z == 0) {
            *(float4*)(g_Q + off)     = *(float4*)&acc[i][0];
            *(float4*)(g_Q + off + 4) = *(float4*)&acc[i][4];
        } else if (z == 2) {
            *(float4*)(g_V + off)     = *(float4*)&acc[i][0];
            *(float4*)(g_V + off + 4) = *(float4*)&acc[i][4];
        } else {
            *(float4*)(g_K + off)     = *(float4*)&acc[i][0];
            *(float4*)(g_K + off + 4) = *(float4*)&acc[i][4];
            const float inv = 1.f / nrm[i];
            float4 o0, o1;
            o0.x = acc[i][0]*inv; o0.y = acc[i][1]*inv;
            o0.z = acc[i][2]*inv; o0.w = acc[i][3]*inv;
            o1.x = acc[i][4]*inv; o1.y = acc[i][5]*inv;
            o1.z = acc[i][6]*inv; o1.w = acc[i][7]*inv;
            *(float4*)(g_Kh + off)     = o0;
            *(float4*)(g_Kh + off + 4) = o1;
        }
    }
}

// ============================================================
// Kernel 2: partial M = K̂^T V ; partial s (fp64).
// ============================================================
__global__ void __launch_bounds__(256) kv_kernel()
{
    extern __shared__ float sm[];
    float* Ks = sm;
    float* Vs = sm + CC*CC;
    const int tid = threadIdx.x;
    const int tx  = tid & 15;
    const int ty  = tid >> 4;
    const int blk = blockIdx.x;
    const size_t base = (size_t)blk * 128 * CC;

    const float4* K4 = (const float4*)(g_Kh + base);
    const float4* V4 = (const float4*)(g_V  + base);
    for (int t = tid; t < 4096; t += 256) {
        ((float4*)Ks)[t] = K4[t];
        ((float4*)Vs)[t] = V4[t];
    }
    __syncthreads();

    float acc[8][8] = {};
    #pragma unroll 4
    for (int n = 0; n < 128; n++) {
        float a[8], bb[8];
        *(float4*)&a[0]  = *(float4*)&Ks[n*CC + ty*8];
        *(float4*)&a[4]  = *(float4*)&Ks[n*CC + ty*8 + 4];
        *(float4*)&bb[0] = *(float4*)&Vs[n*CC + tx*8];
        *(float4*)&bb[4] = *(float4*)&Vs[n*CC + tx*8 + 4];
        #pragma unroll
        for (int i = 0; i < 8; i++)
            #pragma unroll
            for (int j = 0; j < 8; j++)
                acc[i][j] = fmaf(a[i], bb[j], acc[i][j]);
    }

    if (tid < 128) {
        double s = 0.0;
        #pragma unroll 8
        for (int n = 0; n < 128; n++) s += (double)Ks[n*CC + tid];
        g_spart[blk*CC + tid] = s;
    }

    float* Mp = g_Mpart + (size_t)blk*CC*CC;
    #pragma unroll
    for (int i = 0; i < 8; i++) {
        float* mrow = Mp + (size_t)(ty*8 + i)*CC + tx*8;
        *(float4*)mrow       = *(float4*)&acc[i][0];
        *(float4*)(mrow + 4) = *(float4*)&acc[i][4];
    }
}

// ============================================================
__global__ void __launch_bounds__(256) reduce_kernel()
{
    const int idx = blockIdx.x*256 + threadIdx.x;
    const int b = idx >> 14;
    const int e = idx & 16383;
    double a = 0.0;
    #pragma unroll
    for (int p = 0; p < NCHUNK; p++)
        a += (double)g_Mpart[(size_t)((b << 5) + p)*CC*CC + e];
    g_M[idx] = (float)a;

    if (blockIdx.x < 2) {
        const int t2 = blockIdx.x*256 + threadIdx.x;
        const int b2 = t2 >> 7, i2 = t2 & 127;
        double s = 0.0;
        #pragma unroll
        for (int p = 0; p < NCHUNK; p++)
            s += g_spart[((b2 << 5) + p)*CC + i2];
        g_s[t2] = s;
    }
}

// ============================================================
__global__ void __launch_bounds__(128) t_kernel(
    const float* __restrict__ W, const float* __restrict__ bias)
{
    const int b = blockIdx.x;
    const int c = threadIdx.x;
    double t = 0.0;
    for (int d = 0; d < CC; d++)
        t += (double)W[d*CC + c] * g_s[b*CC + d];
    g_t[b*CC + c] = t;
    if (c == 0) {
        double be = 0.0;
        for (int d = 0; d < CC; d++)
            be += (double)bias[d] * g_s[b*CC + d];
        g_beta[b] = be;
    }
}

// ============================================================
// Exact den (fp64) + flag ill-conditioned rows (|den_ref| < 2).
// ============================================================
__global__ void __launch_bounds__(256) den_kernel(const float* __restrict__ x)
{
    const int w = (blockIdx.x << 3) + (threadIdx.x >> 5);
    const int lane = threadIdx.x & 31;
    const int b = w >> 12;
    const float* xr = x + (size_t)w*CC;
    const double* t = g_t + b*CC;
    double s = 0.0;
    #pragma unroll
    for (int u = 0; u < 4; u++)
        s += (double)xr[lane + u*32] * t[lane + u*32];
    #pragma unroll
    for (int off = 16; off; off >>= 1)
        s += __shfl_xor_sync(0xffffffffu, s, off);
    if (lane == 0) {
        const double qn = (double)g_qnorm[w];
        const double num = s + g_beta[b];
        g_den[w] = num + 1e-8 * qn;
        g_flag[w] = (fabs(num / qn) < 2.0) ? 1 : 0;
    }
}

// ============================================================
// Deterministic compaction of flagged rows into ordered per-batch lists.
// Single block, two-pass prefix.
// ============================================================
__global__ void __launch_bounds__(256) compact_kernel()
{
    __shared__ int cnt[256];
    __shared__ int offs[256];
    const int t = threadIdx.x;
    for (int b = 0; b < BB; b++) {
        const int base = b*NN + t*(NN/256);
        int c = 0;
        #pragma unroll
        for (int i = 0; i < NN/256; i++) c += g_flag[base + i];
        cnt[t] = c;
        __syncthreads();
        if (t == 0) {
            int run = 0;
            for (int u = 0; u < 256; u++) { offs[u] = run; run += cnt[u]; }
            g_bcount[b] = run < 256 ? run : 256;
        }
        __syncthreads();
        int o = offs[t];
        #pragma unroll
        for (int i = 0; i < NN/256; i++) {
            const int row = base + i;
            if (g_flag[row]) { if (o < 256) g_list[b*256 + o] = row; o++; }
        }
        __syncthreads();
    }
}

// ============================================================
// Brute den for flagged rows, as a register-tiled GEMM.
// grid (32 key-chunks, 4 batches, 2 row-tiles). Per-score arithmetic
// identical to the reference replica: fp32 ascending-c accumulator,
// fp32 acc/(qn*kn+1e-8f), fp64 key-sum. Partials per (slot, chunk).
// ============================================================
__global__ void __launch_bounds__(256, 1) brute_kernel()
{
    extern __shared__ float sm[];
    float* Qs  = sm;                   // [128c][BSTRIDE] Qs[c][slot]
    float* Kst = sm + 128*BSTRIDE;     // [128c][BSTRIDE] Kst[c][key]
    __shared__ float qn_s[128], kn_s[128];

    const int chunk = blockIdx.x;
    const int b     = blockIdx.y;
    const int tile  = blockIdx.z;
    int cnt = g_bcount[b] - tile*128;
    if (cnt <= 0) return;
    if (cnt > 128) cnt = 128;

    const int tid = threadIdx.x;
    const int tx  = tid & 15;
    const int ty  = tid >> 4;
    const int wid = tid >> 5;
    const int lane = tid & 31;
    const int key0 = b*NN + chunk*128;

    // zero Qs (covers pad slots)
    for (int t = tid; t < 128*BSTRIDE; t += 256) Qs[t] = 0.f;
    __syncthreads();

    // stage flagged Q rows transposed (coalesced LDG per row)
    for (int r = wid; r < cnt; r += 8) {
        const int row = g_list[b*256 + tile*128 + r];
        const float* qr = g_Q + (size_t)row*CC;
        #pragma unroll
        for (int u = 0; u < 4; u++) {
            const int c = lane + u*32;
            Qs[c*BSTRIDE + r] = qr[c];
        }
        if (lane == 0) qn_s[r] = g_qnorm[row];
    }
    for (int r = cnt + tid; r < 128; r += 256) qn_s[r] = 1.f;

    // stage K chunk transposed
    for (int r = wid; r < 128; r += 8) {
        const float* kr = g_K + (size_t)(key0 + r)*CC;
        #pragma unroll
        for (int u = 0; u < 4; u++) {
            const int c = lane + u*32;
            Kst[c*BSTRIDE + r] = kr[c];
        }
        if (lane == 0) kn_s[r] = g_knorm[key0 + r];
    }
    __syncthreads();

    float acc[8][8] = {};
    #pragma unroll 4
    for (int c = 0; c < 128; c++) {
        float a[8], bb[8];
        *(float4*)&a[0]  = *(float4*)&Qs [c*BSTRIDE + ty*8];
        *(float4*)&a[4]  = *(float4*)&Qs [c*BSTRIDE + ty*8 + 4];
        *(float4*)&bb[0] = *(float4*)&Kst[c*BSTRIDE + tx*8];
        *(float4*)&bb[4] = *(float4*)&Kst[c*BSTRIDE + tx*8 + 4];
        #pragma unroll
        for (int i = 0; i < 8; i++)
            #pragma unroll
            for (int j = 0; j < 8; j++)
                acc[i][j] = fmaf(a[i], bb[j], acc[i][j]);
    }

    #pragma unroll
    for (int i = 0; i < 8; i++) {
        const float qn = qn_s[ty*8 + i];
        double dsum = 0.0;
        #pragma unroll
        for (int j = 0; j < 8; j++) {
            const float d = qn * kn_s[tx*8 + j] + 1e-8f;
            dsum += (double)(acc[i][j] / d);
        }
        #pragma unroll
        for (int off = 8; off; off >>= 1)
            dsum += __shfl_xor_sync(0xffffffffu, dsum, off, 16);
        if (tx == 0)
            g_bpart[((size_t)(b*256 + tile*128 + ty*8 + i))*32 + chunk] = dsum;
    }
}

// ============================================================
// Combine brute partials (fixed chunk order) -> final den for flagged rows.
// ============================================================
__global__ void __launch_bounds__(256) combine_kernel()
{
    const int b = blockIdx.x;
    const int idx = threadIdx.x;
    if (idx >= g_bcount[b]) return;
    const int row = g_list[b*256 + idx];
    double s = 0.0;
    #pragma unroll
    for (int c = 0; c < 32; c++)
        s += g_bpart[((size_t)(b*256 + idx))*32 + c];
    g_den[row] = (double)g_qnorm[row] * (s + 1e-8);
}

// ============================================================
__global__ void __launch_bounds__(256, 2) out_kernel(float* __restrict__ out)
{
    extern __shared__ float sm[];
    float* Ms = sm;
    float* Xs = sm + CC*CC;

    const int tid = threadIdx.x;
    const int tx  = tid & 15;
    const int ty  = tid >> 4;
    const int b   = blockIdx.x >> 5;
    const int row0 = blockIdx.x * 128;

    const float4* M4 = (const float4*)(g_M + (size_t)b*CC*CC);
    for (int t = tid; t < 4096; t += 256) ((float4*)Ms)[t] = M4[t];

    float acc[8][8] = {};

    for (int c0 = 0; c0 < CC; c0 += 32) {
        __syncthreads();
        for (int t = tid; t < 128*8; t += 256) {
            int r = t >> 3, cg = t & 7;
            float4 v = *(const float4*)(g_Q + (size_t)(row0 + r)*CC + c0 + cg*4);
            Xs[(cg*4+0)*XS_STRIDE + r] = v.x;
            Xs[(cg*4+1)*XS_STRIDE + r] = v.y;
            Xs[(cg*4+2)*XS_STRIDE + r] = v.z;
            Xs[(cg*4+3)*XS_STRIDE + r] = v.w;
        }
        __syncthreads();
        #pragma unroll 4
        for (int kk = 0; kk < 32; kk++) {
            float a[8], bb[8];
            *(float4*)&a[0]  = *(float4*)&Xs[kk*XS_STRIDE + ty*8];
            *(float4*)&a[4]  = *(float4*)&Xs[kk*XS_STRIDE + ty*8 + 4];
            *(float4*)&bb[0] = *(float4*)&Ms[(c0+kk)*CC + tx*8];
            *(float4*)&bb[4] = *(float4*)&Ms[(c0+kk)*CC + tx*8 + 4];
            #pragma unroll
            for (int i = 0; i < 8; i++)
                #pragma unroll
                for (int j = 0; j < 8; j++)
                    acc[i][j] = fmaf(a[i], bb[j], acc[i][j]);
        }
    }

    #pragma unroll
    for (int i = 0; i < 8; i++) {
        const double inv = 1.0 / g_den[row0 + ty*8 + i];
        float4 o0, o1;
        o0.x = (float)(acc[i][0]*inv); o0.y = (float)(acc[i][1]*inv);
        o0.z = (float)(acc[i][2]*inv); o0.w = (float)(acc[i][3]*inv);
        o1.x = (float)(acc[i][4]*inv); o1.y = (float)(acc[i][5]*inv);
        o1.z = (float)(acc[i][6]*inv); o1.w = (float)(acc[i][7]*inv);
        float* orow = out + (size_t)(row0 + ty*8 + i)*CC + tx*8;
        *(float4*)orow       = o0;
        *(float4*)(orow + 4) = o1;
    }
}

// ============================================================
extern "C" void kernel_launch(void* const* d_in, const int* in_sizes, int n_in,
                              void* d_out, int out_size)
{
    const float* q    = (const float*)d_in[0];
    const float* k    = (const float*)d_in[1];
    const float* v    = (const float*)d_in[2];
    const float* W    = (const float*)d_in[3];
    const float* bias = (const float*)d_in[4];
    float* out = (float*)d_out;

    const size_t sm1 = (size_t)(128 + 32) * XS_STRIDE * sizeof(float);
    const size_t sm2 = (size_t)2 * CC * CC * sizeof(float);
    const size_t sm3 = (size_t)(CC*CC + 32*XS_STRIDE) * sizeof(float);
    const size_t smB = (size_t)2 * 128 * BSTRIDE * sizeof(float);   // 135168

    cudaFuncSetAttribute(proj_kernel,  cudaFuncAttributeMaxDynamicSharedMemorySize, (int)sm1);
    cudaFuncSetAttribute(kv_kernel,    cudaFuncAttributeMaxDynamicSharedMemorySize, (int)sm2);
    cudaFuncSetAttribute(out_kernel,   cudaFuncAttributeMaxDynamicSharedMemorySize, (int)sm3);
    cudaFuncSetAttribute(brute_kernel, cudaFuncAttributeMaxDynamicSharedMemorySize, (int)smB);

    proj_kernel   <<<dim3(NROWS/128, 3), 256, sm1>>>(q, k, v, W, bias);
    kv_kernel     <<<TOTCHUNK, 256, sm2>>>();
    reduce_kernel <<<BB*CC*CC/256, 256>>>();
    t_kernel      <<<BB, 128>>>(W, bias);
    den_kernel    <<<NROWS/8, 256>>>(q);
    compact_kernel<<<1, 256>>>();
    brute_kernel  <<<dim3(32, BB, 2), 256, smB>>>();
    combine_kernel<<<BB, 256>>>();
    out_kernel    <<<NROWS/128, 256, sm3>>>(out);
}

// round 6
// speedup vs baseline: 4.5192x; 1.0851x over previous
#include <cuda_runtime.h>

#define BB 4
#define NN 4096
#define CC 128
#define NROWS (BB*NN)       // 16384
#define NCHUNK 32
#define TOTCHUNK (BB*NCHUNK)
#define XS_STRIDE 132
#define BSTRIDE 132

typedef unsigned long long u64;
__device__ __forceinline__ u64 pack2(float x, float y) {
    u64 r; asm("mov.b64 %0, {%1, %2};" : "=l"(r) : "f"(x), "f"(y)); return r;
}
__device__ __forceinline__ void unpack2(u64 v, float& x, float& y) {
    asm("mov.b64 {%0, %1}, %2;" : "=f"(x), "=f"(y) : "l"(v));
}
__device__ __forceinline__ u64 ffma2(u64 a, u64 b, u64 c) {
    u64 d; asm("fma.rn.f32x2 %0, %1, %2, %3;" : "=l"(d) : "l"(a), "l"(b), "l"(c)); return d;
}

// ---- scratch (device globals) ----
__device__ float  g_Q [NROWS*CC];
__device__ float  g_K [NROWS*CC];
__device__ float  g_Kh[NROWS*CC];
__device__ float  g_V [NROWS*CC];
__device__ float  g_qnorm[NROWS];
__device__ float  g_knorm[NROWS];
__device__ float  g_Mpart[(size_t)TOTCHUNK*CC*CC];
__device__ double g_spart[TOTCHUNK*CC];
__device__ float  g_M[BB*CC*CC];
__device__ double g_s[BB*CC];
__device__ double g_t[BB*CC];
__device__ double g_beta[BB];
__device__ double g_den[NROWS];
__device__ int    g_flag[NROWS];
__device__ int    g_bcount[BB];
__device__ int    g_list[BB*256];
__device__ double g_bpart[BB*256*32];

// ============================================================
// Kernel 1: Y = X @ W^T + b (fp32, ascending-k per-element FMA chain,
// executed as packed f32x2 — bitwise identical to scalar fmaf chain).
// ============================================================
__global__ void __launch_bounds__(256, 1) proj_kernel(
    const float* __restrict__ q_in, const float* __restrict__ k_in,
    const float* __restrict__ v_in, const float* __restrict__ W,
    const float* __restrict__ bias)
{
    extern __shared__ float sm[];
    float* Ws = sm;                     // Ws[c][d] = W[d][c]
    float* Xs = sm + 128*XS_STRIDE;

    const int tid = threadIdx.x;
    const int tx  = tid & 15;
    const int ty  = tid >> 4;
    const int z   = blockIdx.y;
    const float* X = (z == 0) ? q_in : (z == 1) ? k_in : v_in;
    const int row0 = blockIdx.x * 128;

    for (int i = tid; i < CC*CC; i += 256) {
        int d = i >> 7, c = i & 127;
        Ws[c*XS_STRIDE + d] = W[i];
    }

    u64 acc2[8][4];
    #pragma unroll
    for (int i = 0; i < 8; i++)
        #pragma unroll
        for (int jp = 0; jp < 4; jp++) acc2[i][jp] = 0ULL;

    for (int c0 = 0; c0 < CC; c0 += 32) {
        __syncthreads();
        for (int t = tid; t < 128*8; t += 256) {
            int r = t >> 3, cg = t & 7;
            float4 v = *(const float4*)(X + (size_t)(row0 + r)*CC + c0 + cg*4);
            Xs[(cg*4+0)*XS_STRIDE + r] = v.x;
            Xs[(cg*4+1)*XS_STRIDE + r] = v.y;
            Xs[(cg*4+2)*XS_STRIDE + r] = v.z;
            Xs[(cg*4+3)*XS_STRIDE + r] = v.w;
        }
        __syncthreads();
        #pragma unroll 4
        for (int kk = 0; kk < 32; kk++) {
            float a[8];
            *(float4*)&a[0] = *(float4*)&Xs[kk*XS_STRIDE + ty*8];
            *(float4*)&a[4] = *(float4*)&Xs[kk*XS_STRIDE + ty*8 + 4];
            const ulonglong2 bv0 = *(ulonglong2*)&Ws[(c0+kk)*XS_STRIDE + tx*8];
            const ulonglong2 bv1 = *(ulonglong2*)&Ws[(c0+kk)*XS_STRIDE + tx*8 + 4];
            u64 b2[4] = {bv0.x, bv0.y, bv1.x, bv1.y};
            #pragma unroll
            for (int i = 0; i < 8; i++) {
                const u64 as = pack2(a[i], a[i]);
                #pragma unroll
                for (int jp = 0; jp < 4; jp++)
                    acc2[i][jp] = ffma2(as, b2[jp], acc2[i][jp]);
            }
        }
    }

    float acc[8][8];
    #pragma unroll
    for (int i = 0; i < 8; i++)
        #pragma unroll
        for (int jp = 0; jp < 4; jp++)
            unpack2(acc2[i][jp], acc[i][2*jp], acc[i][2*jp+1]);

    float bj[8];
    *(float4*)&bj[0] = *(const float4*)&bias[tx*8];
    *(float4*)&bj[4] = *(const float4*)&bias[tx*8 + 4];
    #pragma unroll
    for (int i = 0; i < 8; i++)
        #pragma unroll
        for (int j = 0; j < 8; j++) acc[i][j] += bj[j];

    float nrm[8];
    if (z < 2) {
        #pragma unroll
        for (int i = 0; i < 8; i++) {
            float sq = 0.f;
            #pragma unroll
            for (int j = 0; j < 8; j++) sq = fmaf(acc[i][j], acc[i][j], sq);
            #pragma unroll
            for (int off = 8; off; off >>= 1)
                sq += __shfl_xor_sync(0xffffffffu, sq, off, 16);
            nrm[i] = sqrtf(sq);
            if (tx == 0) {
                if (z == 0) g_qnorm[row0 + ty*8 + i] = nrm[i];
                else        g_knorm[row0 + ty*8 + i] = nrm[i];
            }
        }
    }

    #pragma unroll
    for (int i = 0; i < 8; i++) {
        const size_t off = (size_t)(row0 + ty*8 + i)*CC + tx*8;
        if (z == 0) {
            *(float4*)(g_Q + off)     = *(float4*)&acc[i][0];
            *(float4*)(g_Q + off + 4) = *(float4*)&acc[i][4];
        } else if (z == 2) {
            *(float4*)(g_V + off)     = *(float4*)&acc[i][0];
            *(float4*)(g_V + off + 4) = *(float4*)&acc[i][4];
        } else {
            *(float4*)(g_K + off)     = *(float4*)&acc[i][0];
            *(float4*)(g_K + off + 4) = *(float4*)&acc[i][4];
            const float inv = 1.f / nrm[i];
            float4 o0, o1;
            o0.x = acc[i][0]*inv; o0.y = acc[i][1]*inv;
            o0.z = acc[i][2]*inv; o0.w = acc[i][3]*inv;
            o1.x = acc[i][4]*inv; o1.y = acc[i][5]*inv;
            o1.z = acc[i][6]*inv; o1.w = acc[i][7]*inv;
            *(float4*)(g_Kh + off)     = o0;
            *(float4*)(g_Kh + off + 4) = o1;
        }
    }
}

// ============================================================
// Kernel 2: partial M = K̂^T V (f32x2) ; partial s (fp64, 4 chains).
// ============================================================
__global__ void __launch_bounds__(256) kv_kernel()
{
    extern __shared__ float sm[];
    float* Ks = sm;
    float* Vs = sm + CC*CC;
    const int tid = threadIdx.x;
    const int tx  = tid & 15;
    const int ty  = tid >> 4;
    const int blk = blockIdx.x;
    const size_t base = (size_t)blk * 128 * CC;

    const float4* K4 = (const float4*)(g_Kh + base);
    const float4* V4 = (const float4*)(g_V  + base);
    for (int t = tid; t < 4096; t += 256) {
        ((float4*)Ks)[t] = K4[t];
        ((float4*)Vs)[t] = V4[t];
    }
    __syncthreads();

    u64 acc2[8][4];
    #pragma unroll
    for (int i = 0; i < 8; i++)
        #pragma unroll
        for (int jp = 0; jp < 4; jp++) acc2[i][jp] = 0ULL;

    #pragma unroll 4
    for (int n = 0; n < 128; n++) {
        float a[8];
        *(float4*)&a[0] = *(float4*)&Ks[n*CC + ty*8];
        *(float4*)&a[4] = *(float4*)&Ks[n*CC + ty*8 + 4];
        const ulonglong2 bv0 = *(ulonglong2*)&Vs[n*CC + tx*8];
        const ulonglong2 bv1 = *(ulonglong2*)&Vs[n*CC + tx*8 + 4];
        u64 b2[4] = {bv0.x, bv0.y, bv1.x, bv1.y};
        #pragma unroll
        for (int i = 0; i < 8; i++) {
            const u64 as = pack2(a[i], a[i]);
            #pragma unroll
            for (int jp = 0; jp < 4; jp++)
                acc2[i][jp] = ffma2(as, b2[jp], acc2[i][jp]);
        }
    }

    if (tid < 128) {
        double s0 = 0.0, s1 = 0.0, s2 = 0.0, s3 = 0.0;
        #pragma unroll 8
        for (int n = 0; n < 128; n += 4) {
            s0 += (double)Ks[(n+0)*CC + tid];
            s1 += (double)Ks[(n+1)*CC + tid];
            s2 += (double)Ks[(n+2)*CC + tid];
            s3 += (double)Ks[(n+3)*CC + tid];
        }
        g_spart[blk*CC + tid] = (s0 + s1) + (s2 + s3);
    }

    float* Mp = g_Mpart + (size_t)blk*CC*CC;
    #pragma unroll
    for (int i = 0; i < 8; i++) {
        float acc[8];
        #pragma unroll
        for (int jp = 0; jp < 4; jp++)
            unpack2(acc2[i][jp], acc[2*jp], acc[2*jp+1]);
        float* mrow = Mp + (size_t)(ty*8 + i)*CC + tx*8;
        *(float4*)mrow       = *(float4*)&acc[0];
        *(float4*)(mrow + 4) = *(float4*)&acc[4];
    }
}

// ============================================================
// Reduction of partials: M in fp32 float4 (numerator-only), s in fp64.
// ============================================================
__global__ void __launch_bounds__(256) reduce_kernel()
{
    const int g = blockIdx.x*256 + threadIdx.x;     // 0..16383 float4 groups
    const int b  = g >> 12;
    const int e4 = g & 4095;
    float4 a = make_float4(0.f, 0.f, 0.f, 0.f);
    #pragma unroll
    for (int p = 0; p < NCHUNK; p++) {
        const float4 v = *(const float4*)&g_Mpart[(((size_t)((b << 5) + p)) << 14) + (e4 << 2)];
        a.x += v.x; a.y += v.y; a.z += v.z; a.w += v.w;
    }
    *(float4*)&g_M[(size_t)g << 2] = a;

    if (g < BB*CC) {
        const int b2 = g >> 7, i2 = g & 127;
        double s0 = 0.0, s1 = 0.0;
        #pragma unroll
        for (int p = 0; p < NCHUNK; p += 2) {
            s0 += g_spart[((b2 << 5) + p  )*CC + i2];
            s1 += g_spart[((b2 << 5) + p+1)*CC + i2];
        }
        g_s[g] = s0 + s1;
    }
}

// ============================================================
// t = W^T s, beta = b.s (fp64). s staged in smem, 4 chains for MLP.
// ============================================================
__global__ void __launch_bounds__(128) t_kernel(
    const float* __restrict__ W, const float* __restrict__ bias)
{
    const int b = blockIdx.x;
    const int c = threadIdx.x;
    __shared__ double ss[128];
    ss[c] = g_s[b*CC + c];
    __syncthreads();

    double t0 = 0.0, t1 = 0.0, t2 = 0.0, t3 = 0.0;
    #pragma unroll 8
    for (int d = 0; d < CC; d += 4) {
        t0 += (double)W[(d+0)*CC + c] * ss[d+0];
        t1 += (double)W[(d+1)*CC + c] * ss[d+1];
        t2 += (double)W[(d+2)*CC + c] * ss[d+2];
        t3 += (double)W[(d+3)*CC + c] * ss[d+3];
    }
    g_t[b*CC + c] = (t0 + t1) + (t2 + t3);

    if (c < 32) {
        double be = 0.0;
        #pragma unroll
        for (int d = c; d < CC; d += 32) be += (double)bias[d] * ss[d];
        #pragma unroll
        for (int off = 16; off; off >>= 1)
            be += __shfl_xor_sync(0xffffffffu, be, off);
        if (c == 0) g_beta[b] = be;
    }
}

// ============================================================
// Exact den (fp64) + flag ill-conditioned rows (|den_ref| < 2).
// ============================================================
__global__ void __launch_bounds__(256) den_kernel(const float* __restrict__ x)
{
    const int w = (blockIdx.x << 3) + (threadIdx.x >> 5);
    const int lane = threadIdx.x & 31;
    const int b = w >> 12;
    const float* xr = x + (size_t)w*CC;
    const double* t = g_t + b*CC;
    double s = 0.0;
    #pragma unroll
    for (int u = 0; u < 4; u++)
        s += (double)xr[lane + u*32] * t[lane + u*32];
    #pragma unroll
    for (int off = 16; off; off >>= 1)
        s += __shfl_xor_sync(0xffffffffu, s, off);
    if (lane == 0) {
        const double qn = (double)g_qnorm[w];
        const double num = s + g_beta[b];
        g_den[w] = num + 1e-8 * qn;
        g_flag[w] = (fabs(num / qn) < 2.0) ? 1 : 0;
    }
}

// ============================================================
// Deterministic compaction of flagged rows (single block, two-pass).
// ============================================================
__global__ void __launch_bounds__(256) compact_kernel()
{
    __shared__ int cnt[256];
    __shared__ int offs[256];
    const int t = threadIdx.x;
    for (int b = 0; b < BB; b++) {
        const int base = b*NN + t*(NN/256);
        int c = 0;
        #pragma unroll
        for (int i = 0; i < NN/256; i++) c += g_flag[base + i];
        cnt[t] = c;
        __syncthreads();
        if (t == 0) {
            int run = 0;
            for (int u = 0; u < 256; u++) { offs[u] = run; run += cnt[u]; }
            g_bcount[b] = run < 256 ? run : 256;
        }
        __syncthreads();
        int o = offs[t];
        #pragma unroll
        for (int i = 0; i < NN/256; i++) {
            const int row = base + i;
            if (g_flag[row]) { if (o < 256) g_list[b*256 + o] = row; o++; }
        }
        __syncthreads();
    }
}

// ============================================================
// Brute den GEMM for flagged rows (f32x2; per-element chain identical
// to reference-replica scalar order).
// ============================================================
__global__ void __launch_bounds__(256, 1) brute_kernel()
{
    extern __shared__ float sm[];
    float* Qs  = sm;                   // [128c][BSTRIDE]
    float* Kst = sm + 128*BSTRIDE;     // [128c][BSTRIDE]
    __shared__ float qn_s[128], kn_s[128];

    const int chunk = blockIdx.x;
    const int b     = blockIdx.y;
    const int tile  = blockIdx.z;
    int cnt = g_bcount[b] - tile*128;
    if (cnt <= 0) return;
    if (cnt > 128) cnt = 128;

    const int tid = threadIdx.x;
    const int tx  = tid & 15;
    const int ty  = tid >> 4;
    const int wid = tid >> 5;
    const int lane = tid & 31;
    const int key0 = b*NN + chunk*128;

    for (int t = tid; t < 128*BSTRIDE; t += 256) Qs[t] = 0.f;
    __syncthreads();

    for (int r = wid; r < cnt; r += 8) {
        const int row = g_list[b*256 + tile*128 + r];
        const float* qr = g_Q + (size_t)row*CC;
        #pragma unroll
        for (int u = 0; u < 4; u++) {
            const int c = lane + u*32;
            Qs[c*BSTRIDE + r] = qr[c];
        }
        if (lane == 0) qn_s[r] = g_qnorm[row];
    }
    for (int r = cnt + tid; r < 128; r += 256) qn_s[r] = 1.f;

    for (int r = wid; r < 128; r += 8) {
        const float* kr = g_K + (size_t)(key0 + r)*CC;
        #pragma unroll
        for (int u = 0; u < 4; u++) {
            const int c = lane + u*32;
            Kst[c*BSTRIDE + r] = kr[c];
        }
        if (lane == 0) kn_s[r] = g_knorm[key0 + r];
    }
    __syncthreads();

    u64 acc2[8][4];
    #pragma unroll
    for (int i = 0; i < 8; i++)
        #pragma unroll
        for (int jp = 0; jp < 4; jp++) acc2[i][jp] = 0ULL;

    #pragma unroll 4
    for (int c = 0; c < 128; c++) {
        float a[8];
        *(float4*)&a[0] = *(float4*)&Qs[c*BSTRIDE + ty*8];
        *(float4*)&a[4] = *(float4*)&Qs[c*BSTRIDE + ty*8 + 4];
        const ulonglong2 bv0 = *(ulonglong2*)&Kst[c*BSTRIDE + tx*8];
        const ulonglong2 bv1 = *(ulonglong2*)&Kst[c*BSTRIDE + tx*8 + 4];
        u64 b2[4] = {bv0.x, bv0.y, bv1.x, bv1.y};
        #pragma unroll
        for (int i = 0; i < 8; i++) {
            const u64 as = pack2(a[i], a[i]);
            #pragma unroll
            for (int jp = 0; jp < 4; jp++)
                acc2[i][jp] = ffma2(as, b2[jp], acc2[i][jp]);
        }
    }

    #pragma unroll
    for (int i = 0; i < 8; i++) {
        float acc[8];
        #pragma unroll
        for (int jp = 0; jp < 4; jp++)
            unpack2(acc2[i][jp], acc[2*jp], acc[2*jp+1]);
        const float qn = qn_s[ty*8 + i];
        double dsum = 0.0;
        #pragma unroll
        for (int j = 0; j < 8; j++) {
            const float d = qn * kn_s[tx*8 + j] + 1e-8f;
            dsum += (double)(acc[j] / d);
        }
        #pragma unroll
        for (int off = 8; off; off >>= 1)
            dsum += __shfl_xor_sync(0xffffffffu, dsum, off, 16);
        if (tx == 0)
            g_bpart[((size_t)(b*256 + tile*128 + ty*8 + i))*32 + chunk] = dsum;
    }
}

// ============================================================
__global__ void __launch_bounds__(256) combine_kernel()
{
    const int b = blockIdx.x;
    const int idx = threadIdx.x;
    if (idx >= g_bcount[b]) return;
    const int row = g_list[b*256 + idx];
    double s = 0.0;
    #pragma unroll
    for (int c = 0; c < 32; c++)
        s += g_bpart[((size_t)(b*256 + idx))*32 + c];
    g_den[row] = (double)g_qnorm[row] * (s + 1e-8);
}

// ============================================================
// out = (q @ M) / den   (f32x2 GEMM)
// ============================================================
__global__ void __launch_bounds__(256, 2) out_kernel(float* __restrict__ out)
{
    extern __shared__ float sm[];
    float* Ms = sm;
    float* Xs = sm + CC*CC;

    const int tid = threadIdx.x;
    const int tx  = tid & 15;
    const int ty  = tid >> 4;
    const int b   = blockIdx.x >> 5;
    const int row0 = blockIdx.x * 128;

    const float4* M4 = (const float4*)(g_M + (size_t)b*CC*CC);
    for (int t = tid; t < 4096; t += 256) ((float4*)Ms)[t] = M4[t];

    u64 acc2[8][4];
    #pragma unroll
    for (int i = 0; i < 8; i++)
        #pragma unroll
        for (int jp = 0; jp < 4; jp++) acc2[i][jp] = 0ULL;

    for (int c0 = 0; c0 < CC; c0 += 32) {
        __syncthreads();
        for (int t = tid; t < 128*8; t += 256) {
            int r = t >> 3, cg = t & 7;
            float4 v = *(const float4*)(g_Q + (size_t)(row0 + r)*CC + c0 + cg*4);
            Xs[(cg*4+0)*XS_STRIDE + r] = v.x;
            Xs[(cg*4+1)*XS_STRIDE + r] = v.y;
            Xs[(cg*4+2)*XS_STRIDE + r] = v.z;
            Xs[(cg*4+3)*XS_STRIDE + r] = v.w;
        }
        __syncthreads();
        #pragma unroll 4
        for (int kk = 0; kk < 32; kk++) {
            float a[8];
            *(float4*)&a[0] = *(float4*)&Xs[kk*XS_STRIDE + ty*8];
            *(float4*)&a[4] = *(float4*)&Xs[kk*XS_STRIDE + ty*8 + 4];
            const ulonglong2 bv0 = *(ulonglong2*)&Ms[(c0+kk)*CC + tx*8];
            const ulonglong2 bv1 = *(ulonglong2*)&Ms[(c0+kk)*CC + tx*8 + 4];
            u64 b2[4] = {bv0.x, bv0.y, bv1.x, bv1.y};
            #pragma unroll
            for (int i = 0; i < 8; i++) {
                const u64 as = pack2(a[i], a[i]);
                #pragma unroll
                for (int jp = 0; jp < 4; jp++)
                    acc2[i][jp] = ffma2(as, b2[jp], acc2[i][jp]);
            }
        }
    }

    #pragma unroll
    for (int i = 0; i < 8; i++) {
        float acc[8];
        #pragma unroll
        for (int jp = 0; jp < 4; jp++)
            unpack2(acc2[i][jp], acc[2*jp], acc[2*jp+1]);
        const double inv = 1.0 / g_den[row0 + ty*8 + i];
        float4 o0, o1;
        o0.x = (float)(acc[0]*inv); o0.y = (float)(acc[1]*inv);
        o0.z = (float)(acc[2]*inv); o0.w = (float)(acc[3]*inv);
        o1.x = (float)(acc[4]*inv); o1.y = (float)(acc[5]*inv);
        o1.z = (float)(acc[6]*inv); o1.w = (float)(acc[7]*inv);
        float* orow = out + (size_t)(row0 + ty*8 + i)*CC + tx*8;
        *(float4*)orow       = o0;
        *(float4*)(orow + 4) = o1;
    }
}

// ============================================================
extern "C" void kernel_launch(void* const* d_in, const int* in_sizes, int n_in,
                              void* d_out, int out_size)
{
    const float* q    = (const float*)d_in[0];
    const float* k    = (const float*)d_in[1];
    const float* v    = (const float*)d_in[2];
    const float* W    = (const float*)d_in[3];
    const float* bias = (const float*)d_in[4];
    float* out = (float*)d_out;

    const size_t sm1 = (size_t)(128 + 32) * XS_STRIDE * sizeof(float);
    const size_t sm2 = (size_t)2 * CC * CC * sizeof(float);
    const size_t sm3 = (size_t)(CC*CC + 32*XS_STRIDE) * sizeof(float);
    const size_t smB = (size_t)2 * 128 * BSTRIDE * sizeof(float);

    cudaFuncSetAttribute(proj_kernel,  cudaFuncAttributeMaxDynamicSharedMemorySize, (int)sm1);
    cudaFuncSetAttribute(kv_kernel,    cudaFuncAttributeMaxDynamicSharedMemorySize, (int)sm2);
    cudaFuncSetAttribute(out_kernel,   cudaFuncAttributeMaxDynamicSharedMemorySize, (int)sm3);
    cudaFuncSetAttribute(brute_kernel, cudaFuncAttributeMaxDynamicSharedMemorySize, (int)smB);

    proj_kernel   <<<dim3(NROWS/128, 3), 256, sm1>>>(q, k, v, W, bias);
    kv_kernel     <<<TOTCHUNK, 256, sm2>>>();
    reduce_kernel <<<BB*CC*CC/(256*4), 256>>>();
    t_kernel      <<<BB, 128>>>(W, bias);
    den_kernel    <<<NROWS/8, 256>>>(q);
    compact_kernel<<<1, 256>>>();
    brute_kernel  <<<dim3(32, BB, 2), 256, smB>>>();
    combine_kernel<<<BB, 256>>>();
    out_kernel    <<<NROWS/128, 256, sm3>>>(out);
}

// round 8
// speedup vs baseline: 4.7386x; 1.0486x over previous
#include <cuda_runtime.h>
#include <cstdint>

#define BB 4
#define NN 4096
#define CC 128
#define NROWS (BB*NN)       // 16384
#define NCHUNK 32
#define TOTCHUNK (BB*NCHUNK)
#define XS_STRIDE 132
#define BSTRIDE 132

typedef unsigned long long u64;
__device__ __forceinline__ u64 pack2(float x, float y) {
    u64 r; asm("mov.b64 %0, {%1, %2};" : "=l"(r) : "f"(x), "f"(y)); return r;
}
__device__ __forceinline__ void unpack2(u64 v, float& x, float& y) {
    asm("mov.b64 {%0, %1}, %2;" : "=f"(x), "=f"(y) : "l"(v));
}
__device__ __forceinline__ u64 ffma2(u64 a, u64 b, u64 c) {
    u64 d; asm("fma.rn.f32x2 %0, %1, %2, %3;" : "=l"(d) : "l"(a), "l"(b), "l"(c)); return d;
}

// ---- scratch (device globals) ----
__device__ float  g_Q [NROWS*CC];
__device__ float  g_K [NROWS*CC];
__device__ float  g_Kh[NROWS*CC];
__device__ float  g_qnorm[NROWS];
__device__ float  g_knorm[NROWS];
__device__ float  g_Gpart[(size_t)TOTCHUNK*CC*CC];   // partial G = K̂^T X_v
__device__ double g_spart[TOTCHUNK*CC];
__device__ float  g_G[BB*CC*CC];                     // G
__device__ float  g_Mfin[BB*CC*CC];                  // M = G W^T + s b^T
__device__ double g_s[BB*CC];
__device__ double g_t[BB*CC];
__device__ double g_beta[BB];
__device__ double g_den[NROWS];
__device__ int    g_flag[NROWS];
__device__ int    g_bcount[BB];
__device__ int    g_list[BB*256];
__device__ double g_bpart[BB*256*32];

// ============================================================
// proj: Y = X @ W^T + b (fp32, ascending-k chain, f32x2).
// z==0: q (+qn). z==1: k (+kn, +k̂). W staged in 32-k chunks -> occ 2.
// ============================================================
__global__ void __launch_bounds__(256, 2) proj_kernel(
    const float* __restrict__ q_in, const float* __restrict__ k_in,
    const float* __restrict__ W, const float* __restrict__ bias)
{
    __shared__ float Wc[32*XS_STRIDE];   // Wc[cc][d] = W[d][c0+cc]
    __shared__ float Xs[32*XS_STRIDE];   // Xs[cc][r]

    const int tid = threadIdx.x;
    const int tx  = tid & 15;
    const int ty  = tid >> 4;
    const int z   = blockIdx.y;
    const float* X = (z == 0) ? q_in : k_in;
    const int row0 = blockIdx.x * 128;

    u64 acc2[8][4];
    #pragma unroll
    for (int i = 0; i < 8; i++)
        #pragma unroll
        for (int jp = 0; jp < 4; jp++) acc2[i][jp] = 0ULL;

    for (int c0 = 0; c0 < CC; c0 += 32) {
        __syncthreads();
        for (int t = tid; t < 128*8; t += 256) {
            int r = t >> 3, cg = t & 7;
            float4 v = *(const float4*)(X + (size_t)(row0 + r)*CC + c0 + cg*4);
            Xs[(cg*4+0)*XS_STRIDE + r] = v.x;
            Xs[(cg*4+1)*XS_STRIDE + r] = v.y;
            Xs[(cg*4+2)*XS_STRIDE + r] = v.z;
            Xs[(cg*4+3)*XS_STRIDE + r] = v.w;
        }
        for (int t = tid; t < 128*8; t += 256) {
            int d = t >> 3, cg = t & 7;
            float4 w = *(const float4*)(W + (size_t)d*CC + c0 + cg*4);
            Wc[(cg*4+0)*XS_STRIDE + d] = w.x;
            Wc[(cg*4+1)*XS_STRIDE + d] = w.y;
            Wc[(cg*4+2)*XS_STRIDE + d] = w.z;
            Wc[(cg*4+3)*XS_STRIDE + d] = w.w;
        }
        __syncthreads();
        #pragma unroll 4
        for (int kk = 0; kk < 32; kk++) {
            float a[8];
            *(float4*)&a[0] = *(float4*)&Xs[kk*XS_STRIDE + ty*8];
            *(float4*)&a[4] = *(float4*)&Xs[kk*XS_STRIDE + ty*8 + 4];
            const ulonglong2 bv0 = *(ulonglong2*)&Wc[kk*XS_STRIDE + tx*8];
            const ulonglong2 bv1 = *(ulonglong2*)&Wc[kk*XS_STRIDE + tx*8 + 4];
            u64 b2[4] = {bv0.x, bv0.y, bv1.x, bv1.y};
            #pragma unroll
            for (int i = 0; i < 8; i++) {
                const u64 as = pack2(a[i], a[i]);
                #pragma unroll
                for (int jp = 0; jp < 4; jp++)
                    acc2[i][jp] = ffma2(as, b2[jp], acc2[i][jp]);
            }
        }
    }

    float acc[8][8];
    #pragma unroll
    for (int i = 0; i < 8; i++)
        #pragma unroll
        for (int jp = 0; jp < 4; jp++)
            unpack2(acc2[i][jp], acc[i][2*jp], acc[i][2*jp+1]);

    float bj[8];
    *(float4*)&bj[0] = *(const float4*)&bias[tx*8];
    *(float4*)&bj[4] = *(const float4*)&bias[tx*8 + 4];
    #pragma unroll
    for (int i = 0; i < 8; i++)
        #pragma unroll
        for (int j = 0; j < 8; j++) acc[i][j] += bj[j];

    float nrm[8];
    #pragma unroll
    for (int i = 0; i < 8; i++) {
        float sq = 0.f;
        #pragma unroll
        for (int j = 0; j < 8; j++) sq = fmaf(acc[i][j], acc[i][j], sq);
        #pragma unroll
        for (int off = 8; off; off >>= 1)
            sq += __shfl_xor_sync(0xffffffffu, sq, off, 16);
        nrm[i] = sqrtf(sq);
        if (tx == 0) {
            if (z == 0) g_qnorm[row0 + ty*8 + i] = nrm[i];
            else        g_knorm[row0 + ty*8 + i] = nrm[i];
        }
    }

    #pragma unroll
    for (int i = 0; i < 8; i++) {
        const size_t off = (size_t)(row0 + ty*8 + i)*CC + tx*8;
        if (z == 0) {
            *(float4*)(g_Q + off)     = *(float4*)&acc[i][0];
            *(float4*)(g_Q + off + 4) = *(float4*)&acc[i][4];
        } else {
            *(float4*)(g_K + off)     = *(float4*)&acc[i][0];
            *(float4*)(g_K + off + 4) = *(float4*)&acc[i][4];
            const float inv = 1.f / nrm[i];
            float4 o0, o1;
            o0.x = acc[i][0]*inv; o0.y = acc[i][1]*inv;
            o0.z = acc[i][2]*inv; o0.w = acc[i][3]*inv;
            o1.x = acc[i][4]*inv; o1.y = acc[i][5]*inv;
            o1.z = acc[i][6]*inv; o1.w = acc[i][7]*inv;
            *(float4*)(g_Kh + off)     = o0;
            *(float4*)(g_Kh + off + 4) = o1;
        }
    }
}

// ============================================================
// kv: partial G = K̂^T X_v over a 128-row chunk (f32x2);
// partial s (fp64, 4 chains). X_v read straight from the input.
// ============================================================
__global__ void __launch_bounds__(256) kv_kernel(const float* __restrict__ v_in)
{
    extern __shared__ float sm[];
    float* Ks = sm;
    float* Vs = sm + CC*CC;
    const int tid = threadIdx.x;
    const int tx  = tid & 15;
    const int ty  = tid >> 4;
    const int blk = blockIdx.x;
    const size_t base = (size_t)blk * 128 * CC;

    const float4* K4 = (const float4*)(g_Kh + base);
    const float4* V4 = (const float4*)(v_in + base);
    for (int t = tid; t < 4096; t += 256) {
        ((float4*)Ks)[t] = K4[t];
        ((float4*)Vs)[t] = V4[t];
    }
    __syncthreads();

    u64 acc2[8][4];
    #pragma unroll
    for (int i = 0; i < 8; i++)
        #pragma unroll
        for (int jp = 0; jp < 4; jp++) acc2[i][jp] = 0ULL;

    #pragma unroll 4
    for (int n = 0; n < 128; n++) {
        float a[8];
        *(float4*)&a[0] = *(float4*)&Ks[n*CC + ty*8];
        *(float4*)&a[4] = *(float4*)&Ks[n*CC + ty*8 + 4];
        const ulonglong2 bv0 = *(ulonglong2*)&Vs[n*CC + tx*8];
        const ulonglong2 bv1 = *(ulonglong2*)&Vs[n*CC + tx*8 + 4];
        u64 b2[4] = {bv0.x, bv0.y, bv1.x, bv1.y};
        #pragma unroll
        for (int i = 0; i < 8; i++) {
            const u64 as = pack2(a[i], a[i]);
            #pragma unroll
            for (int jp = 0; jp < 4; jp++)
                acc2[i][jp] = ffma2(as, b2[jp], acc2[i][jp]);
        }
    }

    if (tid < 128) {
        double s0 = 0.0, s1 = 0.0, s2 = 0.0, s3 = 0.0;
        #pragma unroll 8
        for (int n = 0; n < 128; n += 4) {
            s0 += (double)Ks[(n+0)*CC + tid];
            s1 += (double)Ks[(n+1)*CC + tid];
            s2 += (double)Ks[(n+2)*CC + tid];
            s3 += (double)Ks[(n+3)*CC + tid];
        }
        g_spart[blk*CC + tid] = (s0 + s1) + (s2 + s3);
    }

    float* Gp = g_Gpart + (size_t)blk*CC*CC;
    #pragma unroll
    for (int i = 0; i < 8; i++) {
        float acc[8];
        #pragma unroll
        for (int jp = 0; jp < 4; jp++)
            unpack2(acc2[i][jp], acc[2*jp], acc[2*jp+1]);
        float* grow = Gp + (size_t)(ty*8 + i)*CC + tx*8;
        *(float4*)grow       = *(float4*)&acc[0];
        *(float4*)(grow + 4) = *(float4*)&acc[4];
    }
}

// ============================================================
// Reduce partials: G fp32 float4; s fp64.
// ============================================================
__global__ void __launch_bounds__(256) reduce_kernel()
{
    const int g = blockIdx.x*256 + threadIdx.x;     // 0..16383 float4 groups
    const int b  = g >> 12;
    const int e4 = g & 4095;
    float4 a = make_float4(0.f, 0.f, 0.f, 0.f);
    #pragma unroll
    for (int p = 0; p < NCHUNK; p++) {
        const float4 v = *(const float4*)&g_Gpart[(((size_t)((b << 5) + p)) << 14) + (e4 << 2)];
        a.x += v.x; a.y += v.y; a.z += v.z; a.w += v.w;
    }
    *(float4*)&g_G[(size_t)g << 2] = a;

    if (g < BB*CC) {
        const int b2 = g >> 7, i2 = g & 127;
        double s0 = 0.0, s1 = 0.0;
        #pragma unroll
        for (int p = 0; p < NCHUNK; p += 2) {
            s0 += g_spart[((b2 << 5) + p  )*CC + i2];
            s1 += g_spart[((b2 << 5) + p+1)*CC + i2];
        }
        g_s[g] = s0 + s1;
    }
}

// ============================================================
// t = W^T s (fp64): one warp per output. Blocks 64..67: beta.
// ============================================================
__global__ void __launch_bounds__(256) t_kernel(
    const float* __restrict__ W, const float* __restrict__ bias)
{
    const int wid = threadIdx.x >> 5;
    const int lane = threadIdx.x & 31;
    if (blockIdx.x < 64) {
        const int gidx = blockIdx.x*8 + wid;   // 0..511
        const int b = gidx >> 7, c = gidx & 127;
        double s = 0.0;
        #pragma unroll
        for (int u = 0; u < 4; u++) {
            const int d = lane + u*32;
            s += (double)W[d*CC + c] * g_s[b*CC + d];
        }
        #pragma unroll
        for (int off = 16; off; off >>= 1)
            s += __shfl_xor_sync(0xffffffffu, s, off);
        if (lane == 0) g_t[b*CC + c] = s;
    } else if (wid == 0) {
        const int b = blockIdx.x - 64;
        double be = 0.0;
        #pragma unroll
        for (int u = 0; u < 4; u++) {
            const int d = lane + u*32;
            be += (double)bias[d] * g_s[b*CC + d];
        }
        #pragma unroll
        for (int off = 16; off; off >>= 1)
            be += __shfl_xor_sync(0xffffffffu, be, off);
        if (lane == 0) g_beta[b] = be;
    }
}

// ============================================================
// mk: M[c][d] = sum_e G[c][e] W[d][e] + s_c * b_d.
// grid 16: b = blk>>2, row chunk c0 = (blk&3)*32. 256 threads,
// micro 2x8 (ty: 2 rows, tx: 8 d-cols).
// ============================================================
#define MK_SMEM ((128*XS_STRIDE + 128*36 + 128) * 4)
__global__ void __launch_bounds__(256, 1) mk_kernel(
    const float* __restrict__ W, const float* __restrict__ bias)
{
    extern __shared__ float sm[];
    float* Wt = sm;                        // Wt[e][d] = W[d][e], stride 132
    float* Gt = sm + 128*XS_STRIDE;        // Gt[e][cl], stride 36
    float* sb = Gt + 128*36;               // bias

    const int tid = threadIdx.x;
    const int tx  = tid & 15;
    const int ty  = tid >> 4;
    const int b   = blockIdx.x >> 2;
    const int c0  = (blockIdx.x & 3) * 32;

    for (int i = tid; i < CC*CC; i += 256) {
        int d = i >> 7, e = i & 127;
        Wt[e*XS_STRIDE + d] = W[i];
    }
    for (int i = tid; i < 32*CC; i += 256) {
        int cl = i >> 7, e = i & 127;
        Gt[e*36 + cl] = g_G[(size_t)b*CC*CC + (size_t)(c0 + cl)*CC + e];
    }
    if (tid < 128) sb[tid] = bias[tid];
    __syncthreads();

    float acc[2][8] = {};
    #pragma unroll 4
    for (int e = 0; e < 128; e++) {
        const float a0 = Gt[e*36 + ty*2];
        const float a1 = Gt[e*36 + ty*2 + 1];
        float bb[8];
        *(float4*)&bb[0] = *(float4*)&Wt[e*XS_STRIDE + tx*8];
        *(float4*)&bb[4] = *(float4*)&Wt[e*XS_STRIDE + tx*8 + 4];
        #pragma unroll
        for (int j = 0; j < 8; j++) {
            acc[0][j] = fmaf(a0, bb[j], acc[0][j]);
            acc[1][j] = fmaf(a1, bb[j], acc[1][j]);
        }
    }

    #pragma unroll
    for (int i = 0; i < 2; i++) {
        const int c = c0 + ty*2 + i;
        const float sc = (float)g_s[b*CC + c];
        float4 o0, o1;
        o0.x = fmaf(sc, sb[tx*8+0], acc[i][0]);
        o0.y = fmaf(sc, sb[tx*8+1], acc[i][1]);
        o0.z = fmaf(sc, sb[tx*8+2], acc[i][2]);
        o0.w = fmaf(sc, sb[tx*8+3], acc[i][3]);
        o1.x = fmaf(sc, sb[tx*8+4], acc[i][4]);
        o1.y = fmaf(sc, sb[tx*8+5], acc[i][5]);
        o1.z = fmaf(sc, sb[tx*8+6], acc[i][6]);
        o1.w = fmaf(sc, sb[tx*8+7], acc[i][7]);
        float* mrow = g_Mfin + (size_t)b*CC*CC + (size_t)c*CC + tx*8;
        *(float4*)mrow       = o0;
        *(float4*)(mrow + 4) = o1;
    }
}

// ============================================================
// Exact den (fp64) + flag ill-conditioned rows.
// ============================================================
__global__ void __launch_bounds__(256) den_kernel(const float* __restrict__ x)
{
    const int w = (blockIdx.x << 3) + (threadIdx.x >> 5);
    const int lane = threadIdx.x & 31;
    const int b = w >> 12;
    const float* xr = x + (size_t)w*CC;
    const double* t = g_t + b*CC;
    double s = 0.0;
    #pragma unroll
    for (int u = 0; u < 4; u++)
        s += (double)xr[lane + u*32] * t[lane + u*32];
    #pragma unroll
    for (int off = 16; off; off >>= 1)
        s += __shfl_xor_sync(0xffffffffu, s, off);
    if (lane == 0) {
        const double qn = (double)g_qnorm[w];
        const double num = s + g_beta[b];
        g_den[w] = num + 1e-8 * qn;
        g_flag[w] = (fabs(num / qn) < 2.0) ? 1 : 0;
    }
}

// ============================================================
__global__ void __launch_bounds__(256) compact_kernel()
{
    __shared__ int cnt[256];
    __shared__ int offs[256];
    const int t = threadIdx.x;
    for (int b = 0; b < BB; b++) {
        const int base = b*NN + t*(NN/256);
        int c = 0;
        #pragma unroll
        for (int i = 0; i < NN/256; i++) c += g_flag[base + i];
        cnt[t] = c;
        __syncthreads();
        if (t == 0) {
            int run = 0;
            for (int u = 0; u < 256; u++) { offs[u] = run; run += cnt[u]; }
            g_bcount[b] = run < 256 ? run : 256;
        }
        __syncthreads();
        int o = offs[t];
        #pragma unroll
        for (int i = 0; i < NN/256; i++) {
            const int row = base + i;
            if (g_flag[row]) { if (o < 256) g_list[b*256 + o] = row; o++; }
        }
        __syncthreads();
    }
}

// ============================================================
// Brute den GEMM for flagged rows (reference-replica chains).
// ============================================================
__global__ void __launch_bounds__(256, 1) brute_kernel()
{
    extern __shared__ float sm[];
    float* Qs  = sm;
    float* Kst = sm + 128*BSTRIDE;
    __shared__ float qn_s[128], kn_s[128];

    const int chunk = blockIdx.x;
    const int b     = blockIdx.y;
    const int tile  = blockIdx.z;
    int cnt = g_bcount[b] - tile*128;
    if (cnt <= 0) return;
    if (cnt > 128) cnt = 128;

    const int tid = threadIdx.x;
    const int tx  = tid & 15;
    const int ty  = tid >> 4;
    const int wid = tid >> 5;
    const int lane = tid & 31;
    const int key0 = b*NN + chunk*128;

    for (int t = tid; t < 128*BSTRIDE; t += 256) Qs[t] = 0.f;
    __syncthreads();

    for (int r = wid; r < cnt; r += 8) {
        const int row = g_list[b*256 + tile*128 + r];
        const float* qr = g_Q + (size_t)row*CC;
        #pragma unroll
        for (int u = 0; u < 4; u++) {
            const int c = lane + u*32;
            Qs[c*BSTRIDE + r] = qr[c];
        }
        if (lane == 0) qn_s[r] = g_qnorm[row];
    }
    for (int r = cnt + tid; r < 128; r += 256) qn_s[r] = 1.f;

    for (int r = wid; r < 128; r += 8) {
        const float* kr = g_K + (size_t)(key0 + r)*CC;
        #pragma unroll
        for (int u = 0; u < 4; u++) {
            const int c = lane + u*32;
            Kst[c*BSTRIDE + r] = kr[c];
        }
        if (lane == 0) kn_s[r] = g_knorm[key0 + r];
    }
    __syncthreads();

    u64 acc2[8][4];
    #pragma unroll
    for (int i = 0; i < 8; i++)
        #pragma unroll
        for (int jp = 0; jp < 4; jp++) acc2[i][jp] = 0ULL;

    #pragma unroll 4
    for (int c = 0; c < 128; c++) {
        float a[8];
        *(float4*)&a[0] = *(float4*)&Qs[c*BSTRIDE + ty*8];
        *(float4*)&a[4] = *(float4*)&Qs[c*BSTRIDE + ty*8 + 4];
        const ulonglong2 bv0 = *(ulonglong2*)&Kst[c*BSTRIDE + tx*8];
        const ulonglong2 bv1 = *(ulonglong2*)&Kst[c*BSTRIDE + tx*8 + 4];
        u64 b2[4] = {bv0.x, bv0.y, bv1.x, bv1.y};
        #pragma unroll
        for (int i = 0; i < 8; i++) {
            const u64 as = pack2(a[i], a[i]);
            #pragma unroll
            for (int jp = 0; jp < 4; jp++)
                acc2[i][jp] = ffma2(as, b2[jp], acc2[i][jp]);
        }
    }

    #pragma unroll
    for (int i = 0; i < 8; i++) {
        float acc[8];
        #pragma unroll
        for (int jp = 0; jp < 4; jp++)
            unpack2(acc2[i][jp], acc[2*jp], acc[2*jp+1]);
        const float qn = qn_s[ty*8 + i];
        double dsum = 0.0;
        #pragma unroll
        for (int j = 0; j < 8; j++) {
            const float d = qn * kn_s[tx*8 + j] + 1e-8f;
            dsum += (double)(acc[j] / d);
        }
        #pragma unroll
        for (int off = 8; off; off >>= 1)
            dsum += __shfl_xor_sync(0xffffffffu, dsum, off, 16);
        if (tx == 0)
            g_bpart[((size_t)(b*256 + tile*128 + ty*8 + i))*32 + chunk] = dsum;
    }
}

// ============================================================
__global__ void __launch_bounds__(256) combine_kernel()
{
    const int b = blockIdx.x;
    const int idx = threadIdx.x;
    if (idx >= g_bcount[b]) return;
    const int row = g_list[b*256 + idx];
    double s = 0.0;
    #pragma unroll
    for (int c = 0; c < 32; c++)
        s += g_bpart[((size_t)(b*256 + idx))*32 + c];
    g_den[row] = (double)g_qnorm[row] * (s + 1e-8);
}

// ============================================================
// out = (q @ M) / den   (f32x2 GEMM)
// ============================================================
__global__ void __launch_bounds__(256, 2) out_kernel(float* __restrict__ out)
{
    extern __shared__ float sm[];
    float* Ms = sm;
    float* Xs = sm + CC*CC;

    const int tid = threadIdx.x;
    const int tx  = tid & 15;
    const int ty  = tid >> 4;
    const int b   = blockIdx.x >> 5;
    const int row0 = blockIdx.x * 128;

    const float4* M4 = (const float4*)(g_Mfin + (size_t)b*CC*CC);
    for (int t = tid; t < 4096; t += 256) ((float4*)Ms)[t] = M4[t];

    u64 acc2[8][4];
    #pragma unroll
    for (int i = 0; i < 8; i++)
        #pragma unroll
        for (int jp = 0; jp < 4; jp++) acc2[i][jp] = 0ULL;

    for (int c0 = 0; c0 < CC; c0 += 32) {
        __syncthreads();
        for (int t = tid; t < 128*8; t += 256) {
            int r = t >> 3, cg = t & 7;
            float4 v = *(const float4*)(g_Q + (size_t)(row0 + r)*CC + c0 + cg*4);
            Xs[(cg*4+0)*XS_STRIDE + r] = v.x;
            Xs[(cg*4+1)*XS_STRIDE + r] = v.y;
            Xs[(cg*4+2)*XS_STRIDE + r] = v.z;
            Xs[(cg*4+3)*XS_STRIDE + r] = v.w;
        }
        __syncthreads();
        #pragma unroll 4
        for (int kk = 0; kk < 32; kk++) {
            float a[8];
            *(float4*)&a[0] = *(float4*)&Xs[kk*XS_STRIDE + ty*8];
            *(float4*)&a[4] = *(float4*)&Xs[kk*XS_STRIDE + ty*8 + 4];
            const ulonglong2 bv0 = *(ulonglong2*)&Ms[(c0+kk)*CC + tx*8];
            const ulonglong2 bv1 = *(ulonglong2*)&Ms[(c0+kk)*CC + tx*8 + 4];
            u64 b2[4] = {bv0.x, bv0.y, bv1.x, bv1.y};
            #pragma unroll
            for (int i = 0; i < 8; i++) {
                const u64 as = pack2(a[i], a[i]);
                #pragma unroll
                for (int jp = 0; jp < 4; jp++)
                    acc2[i][jp] = ffma2(as, b2[jp], acc2[i][jp]);
            }
        }
    }

    #pragma unroll
    for (int i = 0; i < 8; i++) {
        float acc[8];
        #pragma unroll
        for (int jp = 0; jp < 4; jp++)
            unpack2(acc2[i][jp], acc[2*jp], acc[2*jp+1]);
        const double inv = 1.0 / g_den[row0 + ty*8 + i];
        float4 o0, o1;
        o0.x = (float)(acc[0]*inv); o0.y = (float)(acc[1]*inv);
        o0.z = (float)(acc[2]*inv); o0.w = (float)(acc[3]*inv);
        o1.x = (float)(acc[4]*inv); o1.y = (float)(acc[5]*inv);
        o1.z = (float)(acc[6]*inv); o1.w = (float)(acc[7]*inv);
        float* orow = out + (size_t)(row0 + ty*8 + i)*CC + tx*8;
        *(float4*)orow       = o0;
        *(float4*)(orow + 4) = o1;
    }
}

// ============================================================
extern "C" void kernel_launch(void* const* d_in, const int* in_sizes, int n_in,
                              void* d_out, int out_size)
{
    const float* q    = (const float*)d_in[0];
    const float* k    = (const float*)d_in[1];
    const float* v    = (const float*)d_in[2];
    const float* W    = (const float*)d_in[3];
    const float* bias = (const float*)d_in[4];
    float* out = (float*)d_out;

    const size_t sm2 = (size_t)2 * CC * CC * sizeof(float);
    const size_t sm3 = (size_t)(CC*CC + 32*XS_STRIDE) * sizeof(float);
    const size_t smB = (size_t)2 * 128 * BSTRIDE * sizeof(float);

    cudaFuncSetAttribute(kv_kernel,    cudaFuncAttributeMaxDynamicSharedMemorySize, (int)sm2);
    cudaFuncSetAttribute(mk_kernel,    cudaFuncAttributeMaxDynamicSharedMemorySize, MK_SMEM);
    cudaFuncSetAttribute(out_kernel,   cudaFuncAttributeMaxDynamicSharedMemorySize, (int)sm3);
    cudaFuncSetAttribute(brute_kernel, cudaFuncAttributeMaxDynamicSharedMemorySize, (int)smB);

    proj_kernel   <<<dim3(NROWS/128, 2), 256>>>(q, k, W, bias);
    kv_kernel     <<<TOTCHUNK, 256, sm2>>>(v);
    reduce_kernel <<<BB*CC*CC/(256*4), 256>>>();
    t_kernel      <<<68, 256>>>(W, bias);
    mk_kernel     <<<16, 256, MK_SMEM>>>(W, bias);
    den_kernel    <<<NROWS/8, 256>>>(q);
    compact_kernel<<<1, 256>>>();
    brute_kernel  <<<dim3(32, BB, 2), 256, smB>>>();
    combine_kernel<<<BB, 256>>>();
    out_kernel    <<<NROWS/128, 256, sm3>>>(out);
}